// round 10
// baseline (speedup 1.0000x reference)
#include <cuda_runtime.h>

// VectorP1FunctionSpace: P1 FEM interpolation on a structured 32x32
// triangulation of [0,1]^2 (nvert = 33*33 = 1089).
//
// basis[v] = min_k relu(x.W[v,k]+c[v,k]) is the P1 hat of vertex v: exactly 0
// outside the containing triangle (relu floor), equal to the barycentric
// coordinate for the 3 triangle vertices. Locate cell analytically, 3
// barycentric weights, gather 3 entries each of wx/wy. Mechanism verified
// exactly in R4 (min-of-6 replication, rel_err 5e-8).
//
// R8 (WIN): smem-stage wx/wy so the data-dependent gathers are LDS not L2.
// R9: (a) float4-vectorized fill (18->5 LDG/thread) to shrink the L1tex
// wavefront queue ahead of the x load, (b) hoist all index/weight math above
// the barrier so the post-barrier tail is just LDS+FMA+STG.

#define NVERT 1089
#define NV4   272   // 1088 / 4 full float4 chunks; element 1088 is the tail

__global__ void __launch_bounds__(128)
VectorP1FunctionSpace_5342939316636_kernel(const float2* __restrict__ x,
                                           const float* __restrict__ wx,
                                           const float* __restrict__ wy,
                                           float2* __restrict__ out,
                                           int n) {
    __shared__ __align__(16) float swx[NVERT];
    __shared__ __align__(16) float swy[NVERT];

    int tid = threadIdx.x;
    int idx = blockIdx.x * blockDim.x + tid;

    // Kick off the independent x load first so it overlaps the table fill.
    float2 p = (idx < n) ? x[idx] : make_float2(0.0f, 0.0f);

    // Vectorized cooperative fill: 272 float4 per table over 128 threads.
    const float4* wx4 = (const float4*)wx;
    const float4* wy4 = (const float4*)wy;
    float4* swx4 = (float4*)swx;
    float4* swy4 = (float4*)swy;
#pragma unroll
    for (int k = tid; k < NV4; k += 128) {
        swx4[k] = __ldg(wx4 + k);
        swy4[k] = __ldg(wy4 + k);
    }
    if (tid == 0) {
        swx[NVERT - 1] = __ldg(wx + NVERT - 1);
        swy[NVERT - 1] = __ldg(wy + NVERT - 1);
    }

    // All index/weight math BEFORE the barrier (independent of the fill).
    float fx = p.x * 32.0f;
    float fy = p.y * 32.0f;
    int i = (int)fx;  i = i < 0 ? 0 : (i > 31 ? 31 : i);
    int j = (int)fy;  j = j < 0 ? 0 : (j > 31 ? 31 : j);
    float u = fx - (float)i;
    float v = fy - (float)j;

    int v00 = i * 33 + j;        // vertex (i,j)
    int v11 = v00 + 34;          // (i+1,j+1) — shared by both triangles

    bool lower = (u >= v);
    int v3 = lower ? (v00 + 33) : (v00 + 1);   // v10 (lower) / v01 (upper)

    float b00 = lower ? (1.0f - u) : (1.0f - v);
    float b11 = lower ? v : u;
    float b3  = lower ? (u - v) : (v - u);

    __syncthreads();

    if (idx >= n) return;

    float ox = fmaf(b00, swx[v00], fmaf(b11, swx[v11], b3 * swx[v3]));
    float oy = fmaf(b00, swy[v00], fmaf(b11, swy[v11], b3 * swy[v3]));

    out[idx] = make_float2(ox, oy);
}

extern "C" void kernel_launch(void* const* d_in, const int* in_sizes, int n_in,
                              void* d_out, int out_size) {
    const float2* x  = (const float2*)d_in[0];  // [B,N,2] fp32
    // d_in[1] = W [1089,6,2], d_in[2] = C [1089,6] — unused (analytic)
    const float*  wx = (const float*)d_in[3];   // [1089]
    const float*  wy = (const float*)d_in[4];   // [1089]
    float2* out = (float2*)d_out;               // [B,N,2] fp32

    int n = in_sizes[0] / 2;  // 16384 points
    int threads = 128;
    int blocks = (n + threads - 1) / threads;   // 128 blocks
    VectorP1FunctionSpace_5342939316636_kernel<<<blocks, threads>>>(
        x, wx, wy, out, n);
}